// round 1
// baseline (speedup 1.0000x reference)
#include <cuda_runtime.h>

// CIN: 3 interaction layers + sum/fc head.
// y[b,h,d] = relu(bias[h] + sum_{m,n} x0[b,m,d] * hprev[b,n,d] * W[m*N+n, h])
// Layer0: hprev = x (N=32, K=1024). Layers1/2: hprev = prev y[:,128:256,:] (N=128, K=4096).
// f[b,j]: j<128 -> y0[:, :128]; j<256 -> y1[:, :128]; j<512 -> y2 (all 256 rows); summed over d.
// out[b] = f[b,:] @ fc_W + fc_b.

#define BATCH 1024
#define MF    32
#define DD    64
#define HH    256

// Inter-layer activations (device scratch; no allocations allowed).
__device__ float g_y0[BATCH * HH * DD];
__device__ float g_y1[BATCH * HH * DD];
__device__ float g_y2[BATCH * HH * DD];

typedef unsigned long long ull;

__device__ __forceinline__ ull pack2(float a, float b) {
    ull r;
    asm("mov.b64 %0, {%1, %2};" : "=l"(r) : "f"(a), "f"(b));
    return r;
}
__device__ __forceinline__ float2 unpack2(ull v) {
    float2 f;
    asm("mov.b64 {%0, %1}, %2;" : "=f"(f.x), "=f"(f.y) : "l"(v));
    return f;
}
// Packed dual-FMA (Blackwell f32x2 pipe): d = a*b + d, lanewise on 2 floats.
__device__ __forceinline__ void ffma2(ull& d, ull a, ull b) {
    asm("fma.rn.f32x2 %0, %1, %2, %0;" : "+l"(d) : "l"(a), "l"(b));
}

// One CIN layer. Grid: 2048 blocks = (batch b) x (h-segment of 128).
// Block: 128 threads. Block tile: 64(d) x 128(h). Thread tile: 4(d) x 16(h).
// K loop in tiles of KT=16; each K-tile has constant m (16 | N_IN), so
// Z[d,k] = x0[m,d] * h[n0+kk, d] needs only 4 FMULs per k per thread.
template <int LAYER, int N_IN>
__global__ void __launch_bounds__(128) cin_layer(const float* __restrict__ x,
                                                 const float* __restrict__ W,
                                                 const float* __restrict__ bias) {
    constexpr int K  = MF * N_IN;
    constexpr int KT = 16;
    constexpr int NT = K / KT;
    constexpr int HB = 128;

    __shared__ __align__(16) float hs[N_IN * DD];   // h tile for this batch
    __shared__ __align__(16) float ws[KT * HB];     // W K-tile, this h-segment

    const int bx   = blockIdx.x;
    const int b    = bx >> 1;
    const int hseg = (bx & 1) * HB;
    const int t    = threadIdx.x;

    // Stage hprev for this batch into SMEM (contiguous rows of 64 floats).
    const float* hsrc;
    if (LAYER == 0)      hsrc = x    + (size_t)b * (MF * DD);
    else if (LAYER == 1) hsrc = g_y0 + (size_t)b * (HH * DD) + 128 * DD;
    else                 hsrc = g_y1 + (size_t)b * (HH * DD) + 128 * DD;

    for (int i = t; i < (N_IN * DD) / 4; i += 128)
        ((float4*)hs)[i] = ((const float4*)hsrc)[i];

    const int d0 = (t & 15) * 4;    // 4 consecutive d per thread
    const int h0 = (t >> 4) * 16;   // 16 consecutive h per thread (8 packed pairs)

    ull acc[4][8];
#pragma unroll
    for (int i = 0; i < 4; i++)
#pragma unroll
        for (int j = 0; j < 8; j++) acc[i][j] = 0ull;  // bit pattern == (0.f, 0.f)

    const float* xb = x + (size_t)b * (MF * DD);

    for (int tile = 0; tile < NT; tile++) {
        const int k0 = tile * KT;
        const int m  = k0 / N_IN;
        const int n0 = k0 % N_IN;   // whole K-tile shares one m row

        // Load W[k0 .. k0+15][hseg .. hseg+127] into SMEM (512 float4s).
#pragma unroll
        for (int i = 0; i < 4; i++) {
            int idx = t + i * 128;        // 0..511
            int row = idx >> 5;           // 0..15
            int c4  = idx & 31;           // float4 column
            ((float4*)ws)[idx] =
                *(const float4*)(W + (size_t)(k0 + row) * HH + hseg + c4 * 4);
        }
        // x0 column for this tile's m (L1-resident after first touch).
        const float4 xv = *(const float4*)(xb + m * DD + d0);
        __syncthreads();

#pragma unroll
        for (int kk = 0; kk < KT; kk++) {
            const float4 hv = *(const float4*)(hs + (n0 + kk) * DD + d0);
            float zs0 = xv.x * hv.x;
            float zs1 = xv.y * hv.y;
            float zs2 = xv.z * hv.z;
            float zs3 = xv.w * hv.w;
            ull zz[4];
            zz[0] = pack2(zs0, zs0);
            zz[1] = pack2(zs1, zs1);
            zz[2] = pack2(zs2, zs2);
            zz[3] = pack2(zs3, zs3);

            ull wp[8];
            {
                const ulonglong2* wr = (const ulonglong2*)(ws + kk * HB + h0);
                ulonglong2 q0 = wr[0], q1 = wr[1], q2 = wr[2], q3 = wr[3];
                wp[0] = q0.x; wp[1] = q0.y;
                wp[2] = q1.x; wp[3] = q1.y;
                wp[4] = q2.x; wp[5] = q2.y;
                wp[6] = q3.x; wp[7] = q3.y;
            }
#pragma unroll
            for (int i = 0; i < 4; i++)
#pragma unroll
                for (int j = 0; j < 8; j++) ffma2(acc[i][j], zz[i], wp[j]);
        }
        __syncthreads();
    }

    // Epilogue: bias + relu, write y[b][h][d] (d contiguous).
    float* yout = (LAYER == 0 ? g_y0 : LAYER == 1 ? g_y1 : g_y2) + (size_t)b * (HH * DD);
#pragma unroll
    for (int i = 0; i < 4; i++) {
#pragma unroll
        for (int j = 0; j < 8; j++) {
            float2 v = unpack2(acc[i][j]);
            int h = hseg + h0 + 2 * j;
            yout[(size_t)h * DD + d0 + i]       = fmaxf(v.x + bias[h], 0.0f);
            yout[(size_t)(h + 1) * DD + d0 + i] = fmaxf(v.y + bias[h + 1], 0.0f);
        }
    }
}

// Head: f[b,j] = sum_d source(j)[b, j', d];  out[b] = f[b,:] @ fcW + fcb.
__global__ void cin_final(const float* __restrict__ fcW,
                          const float* __restrict__ fcb,
                          float* __restrict__ out) {
    const int b = blockIdx.x;
    const int t = threadIdx.x;  // 256 threads

    float p = 0.0f;
    for (int j = t; j < 512; j += 256) {
        const float* src;
        if (j < 128)      src = g_y0 + (size_t)b * (HH * DD) + (size_t)j * DD;
        else if (j < 256) src = g_y1 + (size_t)b * (HH * DD) + (size_t)(j - 128) * DD;
        else              src = g_y2 + (size_t)b * (HH * DD) + (size_t)(j - 256) * DD;
        float s = 0.0f;
#pragma unroll
        for (int d = 0; d < DD; d += 4) {
            float4 v = *(const float4*)(src + d);
            s += (v.x + v.y) + (v.z + v.w);
        }
        p += s * fcW[j];
    }

    __shared__ float red[256];
    red[t] = p;
    __syncthreads();
#pragma unroll
    for (int o = 128; o > 0; o >>= 1) {
        if (t < o) red[t] += red[t + o];
        __syncthreads();
    }
    if (t == 0) out[b] = red[0] + fcb[0];
}

extern "C" void kernel_launch(void* const* d_in, const int* in_sizes, int n_in,
                              void* d_out, int out_size) {
    const float* x   = (const float*)d_in[0];
    const float* W0  = (const float*)d_in[1];
    const float* b0  = (const float*)d_in[2];
    const float* W1  = (const float*)d_in[3];
    const float* b1  = (const float*)d_in[4];
    const float* W2  = (const float*)d_in[5];
    const float* b2  = (const float*)d_in[6];
    const float* fcW = (const float*)d_in[7];
    const float* fcb = (const float*)d_in[8];
    float* out = (float*)d_out;

    cin_layer<0, 32><<<2048, 128>>>(x, W0, b0);
    cin_layer<1, 128><<<2048, 128>>>(x, W1, b1);
    cin_layer<2, 128><<<2048, 128>>>(x, W2, b2);
    cin_final<<<1024, 256>>>(fcW, fcb, out);
}